// round 16
// baseline (speedup 1.0000x reference)
#include <cuda_runtime.h>
#include <cuda_bf16.h>
#include <math.h>

// ---------------- Problem constants ----------------
// B=32, C_IN=1, L=16384, D=64, K=512
// out: [loss(1), recon(32*16385), perplexity(1), indices(131072)] = 655394 floats

#define NROWS   131072
#define IDX_OFF 524322
#define PERP_OFF 524321

typedef unsigned long long ull;

// packed f32x2 helpers (DECODER ONLY — index path stays compiled scalar fp32;
// twice-proven: any hand reassociation of the VQ dot flips tie-sensitive indices)
#define FMA2(d,a,b,c) asm("fma.rn.f32x2 %0, %1, %2, %3;" : "=l"(d) : "l"(a), "l"(b), "l"(c))
__device__ __forceinline__ ull pk2(float v) {
    ull p; unsigned u = __float_as_uint(v);
    asm("mov.b64 %0, {%1, %1};" : "=l"(p) : "r"(u));
    return p;
}
__device__ __forceinline__ void unpk2(ull p, float& lo, float& hi) {
    unsigned a, b;
    asm("mov.b64 {%0, %1}, %2;" : "=r"(a), "=r"(b) : "l"(p));
    lo = __uint_as_float(a); hi = __uint_as_float(b);
}

// ---------------- Scratch (device globals; no allocation) ----------------
__device__ __align__(16) float g_a2[32*4096*64];
__device__ __align__(16) float g_a3[32*4096*128];
__device__ __align__(16) float g_z [NROWS*64];
__device__ __align__(16) float g_wt2[4*32*64];
__device__ __align__(16) float g_wt3[3*64*128];
__device__ __align__(16) float g_wt4[128*64];
__device__ __align__(16) float g_wtd3f[3*64*64];
__device__ __align__(16) float g_wtd4[4*32];
__device__ __align__(16) float g_b3f[64];
__device__ __align__(16) float g_G [3*512*64];
__device__ float g_partial[512];
__device__ int   g_fidx[NROWS];
__device__ int   g_counts[512];

// ---------------- prep: weight re-layout + counts zero + decoder G tables ----------------
// Blocks 0..95: transform work. Blocks 96..607: per-code G build (inputs only).
__global__ __launch_bounds__(256) void prep_kernel(const float* __restrict__ ew2,
                                                   const float* __restrict__ ew3,
                                                   const float* __restrict__ ew4,
                                                   const float* __restrict__ dw2,
                                                   const float* __restrict__ dw3,
                                                   const float* __restrict__ db3,
                                                   const float* __restrict__ dw4,
                                                   const float* __restrict__ emb,
                                                   const float* __restrict__ dw1,
                                                   const float* __restrict__ db1,
                                                   const float* __restrict__ db2,
                                                   float* __restrict__ wt2, float* __restrict__ wt3,
                                                   float* __restrict__ wt4,
                                                   float* __restrict__ wtd3f, float* __restrict__ b3f,
                                                   float* __restrict__ wtd4, int* __restrict__ counts,
                                                   float* __restrict__ G)
{
    __shared__ float es[64];
    __shared__ float e1s[128];
    int tid = threadIdx.x;

    if (blockIdx.x < 96) {
        int i = blockIdx.x * 256 + tid;
        if (i < 512)   counts[i] = 0;
        if (i < 8192)  { int j=i/2048, ci=(i/64)%32, co=i%64;   wt2[i]  = ew2[(co*32+ci)*4 + j]; }
        if (i < 24576) { int j=i/8192, ci=(i/128)%64, co=i%128; wt3[i]  = ew3[(co*64+ci)*3 + j]; }
        if (i < 8192)  { int ci=i/64,  co=i%64;                 wt4[i]  = ew4[co*128 + ci]; }
        if (i < 12288) {
            int j=i/4096, ci=(i/64)%64, cop=i%64;
            int phase = cop >> 5, co = cop & 31;
            int tap = -1;
            if (phase == 0) { if (j == 0) tap = 3; else if (j == 1) tap = 1; }
            else            { if (j == 1) tap = 2; else if (j == 2) tap = 0; }
            wtd3f[i] = (tap >= 0) ? dw3[(ci*32+co)*4 + tap] : 0.f;
        }
        if (i < 128)   { int j=i/32,  ci=i%32;                  wtd4[i] = dw4[ci*4 + j]; }
        if (i < 64)    { b3f[i] = db3[i & 31]; }
        return;
    }

    // ---- G build (one code per block) ----
    int c = blockIdx.x - 96;
    if (tid < 64) es[tid] = emb[c*64 + tid];
    __syncthreads();
    if (tid < 128) {
        float a0 = 0.f, a1 = 0.f, a2 = 0.f, a3 = 0.f;
        #pragma unroll
        for (int ci = 0; ci < 16; ci++) {
            a0 += es[ci     ] * __ldg(&dw1[(ci     )*128 + tid]);
            a1 += es[ci + 16] * __ldg(&dw1[(ci + 16)*128 + tid]);
            a2 += es[ci + 32] * __ldg(&dw1[(ci + 32)*128 + tid]);
            a3 += es[ci + 48] * __ldg(&dw1[(ci + 48)*128 + tid]);
        }
        e1s[tid] = fmaxf((a0 + a1) + (a2 + a3) + db1[tid], 0.f);
    }
    __syncthreads();
    if (tid < 192) {
        int j = tid / 64, t = tid % 64;
        float a0 = 0.f, a1 = 0.f, a2 = 0.f, a3 = 0.f;
        #pragma unroll
        for (int ci = 0; ci < 32; ci++) {
            a0 += e1s[ci     ] * __ldg(&dw2[((ci     )*64 + t)*3 + (2-j)]);
            a1 += e1s[ci + 32] * __ldg(&dw2[((ci + 32)*64 + t)*3 + (2-j)]);
            a2 += e1s[ci + 64] * __ldg(&dw2[((ci + 64)*64 + t)*3 + (2-j)]);
            a3 += e1s[ci + 96] * __ldg(&dw2[((ci + 96)*64 + t)*3 + (2-j)]);
        }
        float acc = (a0 + a1) + (a2 + a3);
        if (j == 1) acc += db2[t];
        G[(j*512 + c)*64 + t] = acc;
    }
}

// ---------------- scalar smem-staged conv (index path — exact R8 FMA chain) ----------------
template<int CIN, int COUT, int K, int S, int P, bool RELU, int TT, int MINB>
__global__ __launch_bounds__(256, MINB) void convSs(const float* __restrict__ in,
                                                    const float* __restrict__ wt,
                                                    const float* __restrict__ bias,
                                                    float* __restrict__ out,
                                                    int Lin, int Lout)
{
    constexpr int C4  = CIN / 4;
    constexpr int CO4 = COUT / 4;
    constexpr int TY  = CO4;
    constexpr int TX  = 256 / TY;
    constexpr int POS  = TX * TT;
    constexpr int PB   = (POS - 1) * S + K;
    constexpr int I4   = PB * C4;
    constexpr int SPAN = (TT - 1) * S + K;

    extern __shared__ float4 is[];
    int tid = threadIdx.x;
    int blockPos = blockIdx.x * POS;
    int b   = blockPos / Lout;
    int t0b = blockPos % Lout;
    int p0b = t0b * S - P;
    const float4* in4 = reinterpret_cast<const float4*>(in);
    for (int i = tid; i < I4; i += 256) {
        int pl = i / C4, c4 = i % C4;
        int p = p0b + pl;
        is[i] = (p >= 0 && p < Lin) ? in4[(b*Lin + p)*C4 + c4]
                                    : make_float4(0.f, 0.f, 0.f, 0.f);
    }
    __syncthreads();

    int ty = tid % TY, tx = tid / TY, tloc = tx * TT;
    const float4* wt4 = reinterpret_cast<const float4*>(wt);

    float4 acc[TT];
    #pragma unroll
    for (int tt = 0; tt < TT; tt++) acc[tt] = make_float4(0.f, 0.f, 0.f, 0.f);

    for (int c4 = 0; c4 < C4; c4++) {
        float4 iv[SPAN];
        #pragma unroll
        for (int s = 0; s < SPAN; s++) iv[s] = is[(tloc*S + s)*C4 + c4];
        #pragma unroll
        for (int j = 0; j < K; j++) {
            float4 w0 = __ldg(&wt4[(j*CIN + c4*4 + 0)*CO4 + ty]);
            float4 w1 = __ldg(&wt4[(j*CIN + c4*4 + 1)*CO4 + ty]);
            float4 w2 = __ldg(&wt4[(j*CIN + c4*4 + 2)*CO4 + ty]);
            float4 w3 = __ldg(&wt4[(j*CIN + c4*4 + 3)*CO4 + ty]);
            #pragma unroll
            for (int tt = 0; tt < TT; tt++) {
                float4 xv = iv[tt*S + j];
                acc[tt].x += w0.x*xv.x + w1.x*xv.y + w2.x*xv.z + w3.x*xv.w;
                acc[tt].y += w0.y*xv.x + w1.y*xv.y + w2.y*xv.z + w3.y*xv.w;
                acc[tt].z += w0.z*xv.x + w1.z*xv.y + w2.z*xv.z + w3.z*xv.w;
                acc[tt].w += w0.w*xv.x + w1.w*xv.y + w2.w*xv.z + w3.w*xv.w;
            }
        }
    }

    float4 bv = reinterpret_cast<const float4*>(bias)[ty];
    float4* out4 = reinterpret_cast<float4*>(out);
    #pragma unroll
    for (int tt = 0; tt < TT; tt++) {
        float4 v;
        v.x = acc[tt].x + bv.x; v.y = acc[tt].y + bv.y;
        v.z = acc[tt].z + bv.z; v.w = acc[tt].w + bv.w;
        if (RELU) {
            v.x = fmaxf(v.x, 0.f); v.y = fmaxf(v.y, 0.f);
            v.z = fmaxf(v.z, 0.f); v.w = fmaxf(v.w, 0.f);
        }
        out4[(b*Lout + t0b + tloc + tt)*CO4 + ty] = v;
    }
}

// ---------------- fused enc1 + enc2 (scalar — index path) ----------------
__global__ __launch_bounds__(256) void enc12_kernel(const float* __restrict__ x,
                                                    const float* __restrict__ w1,
                                                    const float* __restrict__ b1,
                                                    const float* __restrict__ wt2,
                                                    const float* __restrict__ b2,
                                                    float* __restrict__ out)
{
    constexpr int TT = 4, TY = 16, POS = 64, PB = 130, C4 = 8, CO4 = 16, K = 4, S = 2, SPAN = 10;
    __shared__ float4 is[PB*C4];
    __shared__ float  xs[264];
    __shared__ float  w1s[128];
    __shared__ float  b1s[32];

    int tid = threadIdx.x;
    int blockPos = blockIdx.x * POS;
    int b   = blockPos >> 12;
    int t0b = blockPos & 4095;
    int p0b = t0b*2 - 1;
    int xstart = 2*p0b - 1;

    if (tid < 128) w1s[tid] = w1[tid];
    if (tid < 32)  b1s[tid] = b1[tid];
    for (int i = tid; i < 262; i += 256) {
        int xi = xstart + i;
        xs[i] = (xi >= 0 && xi < 16384) ? x[b*16384 + xi] : 0.f;
    }
    __syncthreads();

    for (int i = tid; i < PB*C4; i += 256) {
        int pl = i >> 3, c4 = i & 7;
        int pos = p0b + pl;
        float4 v = make_float4(0.f, 0.f, 0.f, 0.f);
        if (pos >= 0 && pos < 8192) {
            float r[4];
            #pragma unroll
            for (int ch = 0; ch < 4; ch++) {
                int co = c4*4 + ch;
                float acc = b1s[co];
                #pragma unroll
                for (int j = 0; j < 4; j++) acc += w1s[co*4 + j] * xs[2*pl + j];
                r[ch] = fmaxf(acc, 0.f);
            }
            v = make_float4(r[0], r[1], r[2], r[3]);
        }
        is[i] = v;
    }
    __syncthreads();

    int ty = tid % TY, tx = tid / TY, tloc = tx * TT;
    const float4* wt4 = reinterpret_cast<const float4*>(wt2);

    float4 acc[TT];
    #pragma unroll
    for (int t = 0; t < TT; t++) acc[t] = make_float4(0.f, 0.f, 0.f, 0.f);

    for (int c4 = 0; c4 < C4; c4++) {
        float4 iv[SPAN];
        #pragma unroll
        for (int s = 0; s < SPAN; s++) iv[s] = is[(tloc*S + s)*C4 + c4];
        #pragma unroll
        for (int j = 0; j < K; j++) {
            float4 w0 = __ldg(&wt4[(j*32 + c4*4 + 0)*CO4 + ty]);
            float4 w1v = __ldg(&wt4[(j*32 + c4*4 + 1)*CO4 + ty]);
            float4 w2 = __ldg(&wt4[(j*32 + c4*4 + 2)*CO4 + ty]);
            float4 w3 = __ldg(&wt4[(j*32 + c4*4 + 3)*CO4 + ty]);
            #pragma unroll
            for (int t = 0; t < TT; t++) {
                float4 xv = iv[t*S + j];
                acc[t].x += w0.x*xv.x + w1v.x*xv.y + w2.x*xv.z + w3.x*xv.w;
                acc[t].y += w0.y*xv.x + w1v.y*xv.y + w2.y*xv.z + w3.y*xv.w;
                acc[t].z += w0.z*xv.x + w1v.z*xv.y + w2.z*xv.z + w3.z*xv.w;
                acc[t].w += w0.w*xv.x + w1v.w*xv.y + w2.w*xv.z + w3.w*xv.w;
            }
        }
    }

    float4 bv = reinterpret_cast<const float4*>(b2)[ty];
    float4* out4 = reinterpret_cast<float4*>(out);
    #pragma unroll
    for (int t = 0; t < TT; t++) {
        float4 v;
        v.x = fmaxf(acc[t].x + bv.x, 0.f); v.y = fmaxf(acc[t].y + bv.y, 0.f);
        v.z = fmaxf(acc[t].z + bv.z, 0.f); v.w = fmaxf(acc[t].w + bv.w, 0.f);
        out4[(b*4096 + t0b + tloc + t)*CO4 + ty] = v;
    }
}

// ---------------- VQ: exact scalar scan, 8-code ILP (R14 passing version, verbatim) ----------------
__global__ __launch_bounds__(256) void vq2_kernel(const float* __restrict__ z,
                                                  const float* __restrict__ emb,
                                                  float* __restrict__ out,
                                                  int* __restrict__ fidx,
                                                  float* __restrict__ partial,
                                                  int* __restrict__ counts)
{
    __shared__ float4 es[2048];     // 128 codes x 16 float4 = 32KB
    __shared__ float  ek2s[128];
    __shared__ float  red[256];

    int tid = threadIdx.x;
    int row = blockIdx.x * 256 + tid;
    const float4* z4 = reinterpret_cast<const float4*>(z);
    const float4* e4 = reinterpret_cast<const float4*>(emb);

    float4 zv[16];
    #pragma unroll
    for (int dv = 0; dv < 16; dv++) zv[dv] = __ldg(&z4[row*16 + dv]);

    float x2 = 0.f;
    #pragma unroll
    for (int dv = 0; dv < 16; dv++) {
        float4 v = zv[dv];
        x2 += v.x*v.x + v.y*v.y + v.z*v.z + v.w*v.w;
    }

    float best = 3.4e38f;
    int bidx = 0;
    for (int ch = 0; ch < 4; ch++) {
        for (int i = tid; i < 2048; i += 256) es[i] = e4[ch*2048 + i];
        __syncthreads();
        if (tid < 128) {
            float s = 0.f;
            #pragma unroll
            for (int dv = 0; dv < 16; dv++) {
                float4 v = es[tid*16 + dv];
                s += v.x*v.x + v.y*v.y + v.z*v.z + v.w*v.w;
            }
            ek2s[tid] = s;
        }
        __syncthreads();
        for (int c = 0; c < 128; c += 8) {
            float a0 = 0.f, a1 = 0.f, a2 = 0.f, a3 = 0.f;
            float a4 = 0.f, a5 = 0.f, a6 = 0.f, a7 = 0.f;
            #pragma unroll
            for (int dv = 0; dv < 16; dv++) {
                float4 zd = zv[dv];
                float4 e0 = es[(c+0)*16 + dv];
                float4 e1 = es[(c+1)*16 + dv];
                float4 e2 = es[(c+2)*16 + dv];
                float4 e3 = es[(c+3)*16 + dv];
                a0 += e0.x*zd.x + e0.y*zd.y + e0.z*zd.z + e0.w*zd.w;
                a1 += e1.x*zd.x + e1.y*zd.y + e1.z*zd.z + e1.w*zd.w;
                a2 += e2.x*zd.x + e2.y*zd.y + e2.z*zd.z + e2.w*zd.w;
                a3 += e3.x*zd.x + e3.y*zd.y + e3.z*zd.z + e3.w*zd.w;
                float4 e4v = es[(c+4)*16 + dv];
                float4 e5 = es[(c+5)*16 + dv];
                float4 e6 = es[(c+6)*16 + dv];
                float4 e7 = es[(c+7)*16 + dv];
                a4 += e4v.x*zd.x + e4v.y*zd.y + e4v.z*zd.z + e4v.w*zd.w;
                a5 += e5.x*zd.x + e5.y*zd.y + e5.z*zd.z + e5.w*zd.w;
                a6 += e6.x*zd.x + e6.y*zd.y + e6.z*zd.z + e6.w*zd.w;
                a7 += e7.x*zd.x + e7.y*zd.y + e7.z*zd.z + e7.w*zd.w;
            }
            float d0 = (x2 + ek2s[c+0]) - 2.f*a0;
            float d1 = (x2 + ek2s[c+1]) - 2.f*a1;
            float d2 = (x2 + ek2s[c+2]) - 2.f*a2;
            float d3 = (x2 + ek2s[c+3]) - 2.f*a3;
            float d4 = (x2 + ek2s[c+4]) - 2.f*a4;
            float d5 = (x2 + ek2s[c+5]) - 2.f*a5;
            float d6 = (x2 + ek2s[c+6]) - 2.f*a6;
            float d7 = (x2 + ek2s[c+7]) - 2.f*a7;
            int code = ch*128 + c;
            if (d0 < best) { best = d0; bidx = code;     }
            if (d1 < best) { best = d1; bidx = code + 1; }
            if (d2 < best) { best = d2; bidx = code + 2; }
            if (d3 < best) { best = d3; bidx = code + 3; }
            if (d4 < best) { best = d4; bidx = code + 4; }
            if (d5 < best) { best = d5; bidx = code + 5; }
            if (d6 < best) { best = d6; bidx = code + 6; }
            if (d7 < best) { best = d7; bidx = code + 7; }
        }
        __syncthreads();
    }

    out[IDX_OFF + row] = (float)bidx;
    fidx[row] = bidx;
    atomicAdd(&counts[bidx], 1);

    float ls = 0.f;
    #pragma unroll
    for (int dv = 0; dv < 16; dv++) {
        float4 ev = __ldg(&e4[bidx*16 + dv]);
        float4 q = zv[dv];
        float dx = ev.x - q.x, dy = ev.y - q.y, dz = ev.z - q.z, dw = ev.w - q.w;
        ls += dx*dx + dy*dy + dz*dz + dw*dw;
    }
    red[tid] = ls;
    __syncthreads();
    for (int s = 128; s > 0; s >>= 1) {
        if (tid < s) red[tid] += red[tid + s];
        __syncthreads();
    }
    if (tid == 0) partial[blockIdx.x] = red[0];
}

// ---------------- finalize: loss + perplexity ----------------
__global__ void finalize_kernel(const float* __restrict__ partial, const int* __restrict__ counts,
                                float* __restrict__ out)
{
    __shared__ double red[512];
    int tid = threadIdx.x;
    double s = 0.0;
    for (int i = tid; i < 512; i += 512) s += (double)partial[i];
    red[tid] = s;
    __syncthreads();
    for (int st = 256; st > 0; st >>= 1) {
        if (tid < st) red[tid] += red[tid + st];
        __syncthreads();
    }
    if (tid == 0) out[0] = (float)(1.25 * red[0] / 8388608.0);
    __syncthreads();
    double p = (double)counts[tid] / 131072.0;
    double t = p * log(p + 1e-10);
    red[tid] = t;
    __syncthreads();
    for (int st = 256; st > 0; st >>= 1) {
        if (tid < st) red[tid] += red[tid + st];
        __syncthreads();
    }
    if (tid == 0) out[PERP_OFF] = (float)exp(-red[0]);
}

// ---------------- fused dcv3 (G-gather) + dec4: writes recon directly ----------------
__global__ __launch_bounds__(256) void dcv34_kernel(const int* __restrict__ fidx,
                                                    const float* __restrict__ G,
                                                    const float* __restrict__ wt,
                                                    const float* __restrict__ bias,
                                                    const float* __restrict__ wt4d,
                                                    const float* __restrict__ b4d,
                                                    float* __restrict__ out)
{
    constexpr int C4 = 16, CO4 = 16, TY = 16, TT = 4, POS = 64, PB = 67, I4 = PB*C4, SPAN = 6;
    __shared__ float4 is[I4];
    __shared__ float4 res[POS*16];
    __shared__ float4 halo[8];
    __shared__ float4 ws4[32];

    int tid = threadIdx.x;
    int blockPos = blockIdx.x * POS;
    int t0b = blockPos & 4095;
    int bbase = blockPos - t0b;
    int b = bbase >> 12;
    int p0b = t0b - 2;
    const float4* G4 = reinterpret_cast<const float4*>(G);

    if (tid < 32) ws4[tid] = reinterpret_cast<const float4*>(wt4d)[tid];

    for (int i = tid; i < I4; i += 256) {
        int pl = i >> 4, c4 = i & 15;
        int p = p0b + pl;
        float4 v = make_float4(0.f, 0.f, 0.f, 0.f);
        if (p >= 0 && p < 4096) {
            int r = bbase + p;
            int cc = fidx[r];
            v = __ldg(&G4[(512 + cc)*16 + c4]);
            if (p > 0) {
                int cm = fidx[r-1];
                float4 g = __ldg(&G4[cm*16 + c4]);
                v.x += g.x; v.y += g.y; v.z += g.z; v.w += g.w;
            }
            if (p < 4095) {
                int cp = fidx[r+1];
                float4 g = __ldg(&G4[(1024 + cp)*16 + c4]);
                v.x += g.x; v.y += g.y; v.z += g.z; v.w += g.w;
            }
            v.x = fmaxf(v.x, 0.f); v.y = fmaxf(v.y, 0.f);
            v.z = fmaxf(v.z, 0.f); v.w = fmaxf(v.w, 0.f);
        }
        is[i] = v;
    }
    __syncthreads();

    int ty = tid % TY, tx = tid / TY, tloc = tx * TT;
    const float4* wt4 = reinterpret_cast<const float4*>(wt);

    if (tid < 8 && t0b > 0) {
        int q = tid + 8;
        ull h01 = 0ull, h23 = 0ull;
        for (int c4 = 0; c4 < C4; c4++) {
            #pragma unroll
            for (int j = 0; j < 3; j++) {
                float4 xv = is[j*C4 + c4];
                float4 w0 = __ldg(&wt4[(j*64 + c4*4 + 0)*CO4 + q]);
                float4 w1 = __ldg(&wt4[(j*64 + c4*4 + 1)*CO4 + q]);
                float4 w2 = __ldg(&wt4[(j*64 + c4*4 + 2)*CO4 + q]);
                float4 w3 = __ldg(&wt4[(j*64 + c4*4 + 3)*CO4 + q]);
                ulonglong2 p0 = *reinterpret_cast<ulonglong2*>(&w0);
                ulonglong2 p1 = *reinterpret_cast<ulonglong2*>(&w1);
                ulonglong2 p2 = *reinterpret_cast<ulonglong2*>(&w2);
                ulonglong2 p3 = *reinterpret_cast<ulonglong2*>(&w3);
                ull d;
                d = pk2(xv.x); FMA2(h01, p0.x, d, h01); FMA2(h23, p0.y, d, h23);
                d = pk2(xv.y); FMA2(h01, p1.x, d, h01); FMA2(h23, p1.y, d, h23);
                d = pk2(xv.z); FMA2(h01, p2.x, d, h01); FMA2(h23, p2.y, d, h23);
                d = pk2(xv.w); FMA2(h01, p3.x, d, h01); FMA2(h23, p3.y, d, h23);
            }
        }
        float4 bv = reinterpret_cast<const float4*>(bias)[q];
        float x0, x1, x2, x3;
        unpk2(h01, x0, x1);
        unpk2(h23, x2, x3);
        float4 v;
        v.x = fmaxf(x0 + bv.x, 0.f); v.y = fmaxf(x1 + bv.y, 0.f);
        v.z = fmaxf(x2 + bv.z, 0.f); v.w = fmaxf(x3 + bv.w, 0.f);
        halo[tid] = v;
    }

    {
        ull a01[TT], a23[TT];
        #pragma unroll
        for (int t = 0; t < TT; t++) { a01[t] = 0ull; a23[t] = 0ull; }

        for (int c4 = 0; c4 < C4; c4++) {
            float4 iv[SPAN];
            #pragma unroll
            for (int s = 0; s < SPAN; s++) iv[s] = is[(tloc + 1 + s)*C4 + c4];
            #pragma unroll
            for (int j = 0; j < 3; j++) {
                float4 w0 = __ldg(&wt4[(j*64 + c4*4 + 0)*CO4 + ty]);
                float4 w1 = __ldg(&wt4[(j*64 + c4*4 + 1)*CO4 + ty]);
                float4 w2 = __ldg(&wt4[(j*64 + c4*4 + 2)*CO4 + ty]);
                float4 w3 = __ldg(&wt4[(j*64 + c4*4 + 3)*CO4 + ty]);
                ulonglong2 p0 = *reinterpret_cast<ulonglong2*>(&w0);
                ulonglong2 p1 = *reinterpret_cast<ulonglong2*>(&w1);
                ulonglong2 p2 = *reinterpret_cast<ulonglong2*>(&w2);
                ulonglong2 p3 = *reinterpret_cast<ulonglong2*>(&w3);
                #pragma unroll
                for (int t = 0; t < TT; t++) {
                    float4 xv = iv[t + j];
                    ull d;
                    d = pk2(xv.x); FMA2(a01[t], p0.x, d, a01[t]); FMA2(a23[t], p0.y, d, a23[t]);
                    d = pk2(xv.y); FMA2(a01[t], p1.x, d, a01[t]); FMA2(a23[t], p1.y, d, a23[t]);
                    d = pk2(xv.z); FMA2(a01[t], p2.x, d, a01[t]); FMA2(a23[t], p2.y, d, a23[t]);
                    d = pk2(xv.w); FMA2(a01[t], p3.x, d, a01[t]); FMA2(a23[t], p3.y, d, a23[t]);
                }
            }
        }

        float4 bv = reinterpret_cast<const float4*>(bias)[ty];
        #pragma unroll
        for (int t = 0; t < TT; t++) {
            float x0, x1, x2, x3;
            unpk2(a01[t], x0, x1);
            unpk2(a23[t], x2, x3);
            float4 v;
            v.x = fmaxf(x0 + bv.x, 0.f); v.y = fmaxf(x1 + bv.y, 0.f);
            v.z = fmaxf(x2 + bv.z, 0.f); v.w = fmaxf(x3 + bv.w, 0.f);
            res[(tloc + t)*16 + ty] = v;
        }
    }
    __syncthreads();

    float b4 = b4d[0];
    int D0 = 2*t0b;
    int l = 4*t0b - 1 + tid;
    if (l >= 0 && l <= 16384) {
        float acc = 0.f;
        int j0 = (l + 1) & 1;
        #pragma unroll
        for (int jj = 0; jj < 2; jj++) {
            int j = j0 + 2*jj;
            int num = l + 1 - j;
            if (num >= 0) {
                int t = num >> 1;
                if (t < 8192) {
                    int dt = t - D0;
                    const float4* src = (dt < 0) ? halo
                                                 : &res[(dt >> 1)*16 + (dt & 1)*8];
                    #pragma unroll
                    for (int c4 = 0; c4 < 8; c4++) {
                        float4 wv = ws4[j*8 + c4];
                        float4 xv = src[c4];
                        acc += wv.x*xv.x + wv.y*xv.y + wv.z*xv.z + wv.w*xv.w;
                    }
                }
            }
        }
        out[1 + b*16385 + l] = acc + b4;
    }
    if (t0b == 4032 && tid < 2) {
        int l2 = 16383 + tid;
        float acc = 0.f;
        int j0 = (l2 + 1) & 1;
        #pragma unroll
        for (int jj = 0; jj < 2; jj++) {
            int j = j0 + 2*jj;
            int num = l2 + 1 - j;
            if (num >= 0) {
                int t = num >> 1;
                if (t < 8192) {
                    int dt = t - D0;
                    const float4* src = &res[(dt >> 1)*16 + (dt & 1)*8];
                    #pragma unroll
                    for (int c4 = 0; c4 < 8; c4++) {
                        float4 wv = ws4[j*8 + c4];
                        float4 xv = src[c4];
                        acc += wv.x*xv.x + wv.y*xv.y + wv.z*xv.z + wv.w*xv.w;
                    }
                }
            }
        }
        out[1 + b*16385 + l2] = acc + b4;
    }
}

// ---------------- launch ----------------
extern "C" void kernel_launch(void* const* d_in, const int* in_sizes, int n_in,
                              void* d_out, int out_size)
{
    const float* x   = (const float*)d_in[0];
    const float* ew1 = (const float*)d_in[1];
    const float* eb1 = (const float*)d_in[2];
    const float* ew2 = (const float*)d_in[3];
    const float* eb2 = (const float*)d_in[4];
    const float* ew3 = (const float*)d_in[5];
    const float* eb3 = (const float*)d_in[6];
    const float* ew4 = (const float*)d_in[7];
    const float* eb4 = (const float*)d_in[8];
    const float* dw1 = (const float*)d_in[9];
    const float* db1 = (const float*)d_in[10];
    const float* dw2 = (const float*)d_in[11];
    const float* db2 = (const float*)d_in[12];
    const float* dw3 = (const float*)d_in[13];
    const float* db3 = (const float*)d_in[14];
    const float* dw4 = (const float*)d_in[15];
    const float* db4 = (const float*)d_in[16];
    const float* emb = (const float*)d_in[17];
    float* out = (float*)d_out;

    float *a2, *a3, *z;
    float *wt2, *wt3, *wt4, *wtd3f, *wtd4, *b3f, *G, *partial;
    int *counts, *fidx;
    cudaGetSymbolAddress((void**)&a2,    g_a2);
    cudaGetSymbolAddress((void**)&a3,    g_a3);
    cudaGetSymbolAddress((void**)&z,     g_z);
    cudaGetSymbolAddress((void**)&wt2,   g_wt2);
    cudaGetSymbolAddress((void**)&wt3,   g_wt3);
    cudaGetSymbolAddress((void**)&wt4,   g_wt4);
    cudaGetSymbolAddress((void**)&wtd3f, g_wtd3f);
    cudaGetSymbolAddress((void**)&wtd4,  g_wtd4);
    cudaGetSymbolAddress((void**)&b3f,   g_b3f);
    cudaGetSymbolAddress((void**)&G,     g_G);
    cudaGetSymbolAddress((void**)&partial, g_partial);
    cudaGetSymbolAddress((void**)&counts,  g_counts);
    cudaGetSymbolAddress((void**)&fidx,    g_fidx);

    auto enc4 = convSs<128, 64, 1, 1, 0, false, 8, 2>;
    cudaFuncSetAttribute(enc4, cudaFuncAttributeMaxDynamicSharedMemorySize, 128*32*16);

    // prep: weight layouts + counts zero + decoder G tables (one kernel)
    prep_kernel<<<608, 256>>>(ew2, ew3, ew4, dw2, dw3, db3, dw4, emb, dw1, db1, db2,
                              wt2, wt3, wt4, wtd3f, b3f, wtd4, counts, G);

    // encoder — scalar fp32 (index-determining path; per-output chains identical to R8)
    enc12_kernel<<<2048, 256>>>(x, ew1, eb1, wt2, eb2, a2);
    convSs<64, 128, 3, 1, 1, true, 4, 4><<<4096, 256, 34*16*16>>>(a2, wt3, eb3, a3, 4096, 4096);
    enc4<<<1024, 256, 128*32*16>>>(a3, wt4, eb4, z, 4096, 4096);

    // vq — exact scalar scan, 8-code ILP (compiled association = ground truth)
    vq2_kernel<<<512, 256>>>(z, emb, out, fidx, partial, counts);
    finalize_kernel<<<1, 512>>>(partial, counts, out);

    // decoder — fused G-gather conv + dec4, writes recon directly
    dcv34_kernel<<<2048, 256>>>(fidx, G, wtd3f, b3f, wtd4, db4, out);
}

// round 17
// speedup vs baseline: 1.0527x; 1.0527x over previous
#include <cuda_runtime.h>
#include <cuda_bf16.h>
#include <math.h>

// ---------------- Problem constants ----------------
// B=32, C_IN=1, L=16384, D=64, K=512
// out: [loss(1), recon(32*16385), perplexity(1), indices(131072)] = 655394 floats

#define NROWS   131072
#define IDX_OFF 524322
#define PERP_OFF 524321

typedef unsigned long long ull;

// packed f32x2 helpers (DECODER ONLY — index path stays compiled scalar fp32)
#define FMA2(d,a,b,c) asm("fma.rn.f32x2 %0, %1, %2, %3;" : "=l"(d) : "l"(a), "l"(b), "l"(c))
__device__ __forceinline__ ull pk2(float v) {
    ull p; unsigned u = __float_as_uint(v);
    asm("mov.b64 %0, {%1, %1};" : "=l"(p) : "r"(u));
    return p;
}
__device__ __forceinline__ void unpk2(ull p, float& lo, float& hi) {
    unsigned a, b;
    asm("mov.b64 {%0, %1}, %2;" : "=r"(a), "=r"(b) : "l"(p));
    lo = __uint_as_float(a); hi = __uint_as_float(b);
}

// ---------------- Scratch (device globals; no allocation) ----------------
__device__ __align__(16) float g_a2[32*4096*64];
__device__ __align__(16) float g_a3[32*4096*128];
__device__ __align__(16) float g_z [NROWS*64];
__device__ __align__(16) float g_wt2[4*32*64];
__device__ __align__(16) float g_wt3[3*64*128];
__device__ __align__(16) float g_wt4[128*64];
__device__ __align__(16) float g_wtd2[3*128*64];
__device__ __align__(16) float g_wtd3f[3*64*64];
__device__ __align__(16) float g_wtd4[4*32];
__device__ __align__(16) float g_b3f[64];
__device__ __align__(16) float g_G [3*512*64];
__device__ float g_partial[512];
__device__ int   g_fidx[NROWS];
__device__ int   g_counts[512];

// ---------------- Weight re-layout: wt[(j*CIN+ci)*COUT + co] (+ counts zero) ----------------
__global__ void transform_kernel(const float* __restrict__ ew2, const float* __restrict__ ew3,
                                 const float* __restrict__ ew4,
                                 const float* __restrict__ dw2,
                                 const float* __restrict__ dw3, const float* __restrict__ db3,
                                 const float* __restrict__ dw4,
                                 float* __restrict__ wt2, float* __restrict__ wt3,
                                 float* __restrict__ wt4,
                                 float* __restrict__ wtd2,
                                 float* __restrict__ wtd3f, float* __restrict__ b3f,
                                 float* __restrict__ wtd4, int* __restrict__ counts)
{
    int i = blockIdx.x * blockDim.x + threadIdx.x;
    if (i < 512)   counts[i] = 0;
    if (i < 8192)  { int j=i/2048, ci=(i/64)%32, co=i%64;   wt2[i]  = ew2[(co*32+ci)*4 + j]; }
    if (i < 24576) { int j=i/8192, ci=(i/128)%64, co=i%128; wt3[i]  = ew3[(co*64+ci)*3 + j]; }
    if (i < 8192)  { int ci=i/64,  co=i%64;                 wt4[i]  = ew4[co*128 + ci]; }
    if (i < 24576) { int j=i/8192, ci=(i/64)%128, co=i%64;  wtd2[i] = dw2[(ci*64+co)*3 + (2-j)]; }
    if (i < 12288) {
        int j=i/4096, ci=(i/64)%64, cop=i%64;
        int phase = cop >> 5, co = cop & 31;
        int tap = -1;
        if (phase == 0) { if (j == 0) tap = 3; else if (j == 1) tap = 1; }
        else            { if (j == 1) tap = 2; else if (j == 2) tap = 0; }
        wtd3f[i] = (tap >= 0) ? dw3[(ci*32+co)*4 + tap] : 0.f;
    }
    if (i < 128)   { int j=i/32,  ci=i%32;                  wtd4[i] = dw4[ci*4 + j]; }
    if (i < 64)    { b3f[i] = db3[i & 31]; }
}

// ---------------- fused decoder code-table precompute: E1 (smem) -> G ----------------
__global__ __launch_bounds__(192) void build_EG_kernel(const float* __restrict__ emb,
                                                       const float* __restrict__ dw1,
                                                       const float* __restrict__ db1,
                                                       const float* __restrict__ wtd2,
                                                       const float* __restrict__ db2,
                                                       float* __restrict__ G)
{
    __shared__ float es[64];
    __shared__ float e1s[128];
    int c = blockIdx.x;
    int tid = threadIdx.x;
    if (tid < 64) es[tid] = emb[c*64 + tid];
    __syncthreads();
    if (tid < 128) {
        float a0 = 0.f, a1 = 0.f, a2 = 0.f, a3 = 0.f;
        #pragma unroll
        for (int ci = 0; ci < 16; ci++) {
            a0 += es[ci     ] * __ldg(&dw1[(ci     )*128 + tid]);
            a1 += es[ci + 16] * __ldg(&dw1[(ci + 16)*128 + tid]);
            a2 += es[ci + 32] * __ldg(&dw1[(ci + 32)*128 + tid]);
            a3 += es[ci + 48] * __ldg(&dw1[(ci + 48)*128 + tid]);
        }
        e1s[tid] = fmaxf((a0 + a1) + (a2 + a3) + db1[tid], 0.f);
    }
    __syncthreads();
    int j = tid / 64, t = tid % 64;
    float a0 = 0.f, a1 = 0.f, a2 = 0.f, a3 = 0.f;
    int base = j*128;
    #pragma unroll
    for (int ci = 0; ci < 32; ci++) {
        a0 += e1s[ci     ] * __ldg(&wtd2[(base + ci     )*64 + t]);
        a1 += e1s[ci + 32] * __ldg(&wtd2[(base + ci + 32)*64 + t]);
        a2 += e1s[ci + 64] * __ldg(&wtd2[(base + ci + 64)*64 + t]);
        a3 += e1s[ci + 96] * __ldg(&wtd2[(base + ci + 96)*64 + t]);
    }
    float acc = (a0 + a1) + (a2 + a3);
    if (j == 1) acc += db2[t];
    G[(j*512 + c)*64 + t] = acc;
}

// ---------------- scalar smem-staged conv (index path — exact R8 FMA chain) ----------------
template<int CIN, int COUT, int K, int S, int P, bool RELU, int TT, int MINB>
__global__ __launch_bounds__(256, MINB) void convSs(const float* __restrict__ in,
                                                    const float* __restrict__ wt,
                                                    const float* __restrict__ bias,
                                                    float* __restrict__ out,
                                                    int Lin, int Lout)
{
    constexpr int C4  = CIN / 4;
    constexpr int CO4 = COUT / 4;
    constexpr int TY  = CO4;
    constexpr int TX  = 256 / TY;
    constexpr int POS  = TX * TT;
    constexpr int PB   = (POS - 1) * S + K;
    constexpr int I4   = PB * C4;
    constexpr int SPAN = (TT - 1) * S + K;

    extern __shared__ float4 is[];
    int tid = threadIdx.x;
    int blockPos = blockIdx.x * POS;
    int b   = blockPos / Lout;
    int t0b = blockPos % Lout;
    int p0b = t0b * S - P;
    const float4* in4 = reinterpret_cast<const float4*>(in);
    for (int i = tid; i < I4; i += 256) {
        int pl = i / C4, c4 = i % C4;
        int p = p0b + pl;
        is[i] = (p >= 0 && p < Lin) ? in4[(b*Lin + p)*C4 + c4]
                                    : make_float4(0.f, 0.f, 0.f, 0.f);
    }
    __syncthreads();

    int ty = tid % TY, tx = tid / TY, tloc = tx * TT;
    const float4* wt4 = reinterpret_cast<const float4*>(wt);

    float4 acc[TT];
    #pragma unroll
    for (int tt = 0; tt < TT; tt++) acc[tt] = make_float4(0.f, 0.f, 0.f, 0.f);

    for (int c4 = 0; c4 < C4; c4++) {
        float4 iv[SPAN];
        #pragma unroll
        for (int s = 0; s < SPAN; s++) iv[s] = is[(tloc*S + s)*C4 + c4];
        #pragma unroll
        for (int j = 0; j < K; j++) {
            float4 w0 = __ldg(&wt4[(j*CIN + c4*4 + 0)*CO4 + ty]);
            float4 w1 = __ldg(&wt4[(j*CIN + c4*4 + 1)*CO4 + ty]);
            float4 w2 = __ldg(&wt4[(j*CIN + c4*4 + 2)*CO4 + ty]);
            float4 w3 = __ldg(&wt4[(j*CIN + c4*4 + 3)*CO4 + ty]);
            #pragma unroll
            for (int tt = 0; tt < TT; tt++) {
                float4 xv = iv[tt*S + j];
                acc[tt].x += w0.x*xv.x + w1.x*xv.y + w2.x*xv.z + w3.x*xv.w;
                acc[tt].y += w0.y*xv.x + w1.y*xv.y + w2.y*xv.z + w3.y*xv.w;
                acc[tt].z += w0.z*xv.x + w1.z*xv.y + w2.z*xv.z + w3.z*xv.w;
                acc[tt].w += w0.w*xv.x + w1.w*xv.y + w2.w*xv.z + w3.w*xv.w;
            }
        }
    }

    float4 bv = reinterpret_cast<const float4*>(bias)[ty];
    float4* out4 = reinterpret_cast<float4*>(out);
    #pragma unroll
    for (int tt = 0; tt < TT; tt++) {
        float4 v;
        v.x = acc[tt].x + bv.x; v.y = acc[tt].y + bv.y;
        v.z = acc[tt].z + bv.z; v.w = acc[tt].w + bv.w;
        if (RELU) {
            v.x = fmaxf(v.x, 0.f); v.y = fmaxf(v.y, 0.f);
            v.z = fmaxf(v.z, 0.f); v.w = fmaxf(v.w, 0.f);
        }
        out4[(b*Lout + t0b + tloc + tt)*CO4 + ty] = v;
    }
}

// ---------------- fused enc1 + enc2 (scalar — index path) ----------------
__global__ __launch_bounds__(256) void enc12_kernel(const float* __restrict__ x,
                                                    const float* __restrict__ w1,
                                                    const float* __restrict__ b1,
                                                    const float* __restrict__ wt2,
                                                    const float* __restrict__ b2,
                                                    float* __restrict__ out)
{
    constexpr int TT = 4, TY = 16, POS = 64, PB = 130, C4 = 8, CO4 = 16, K = 4, S = 2, SPAN = 10;
    __shared__ float4 is[PB*C4];
    __shared__ float  xs[264];
    __shared__ float  w1s[128];
    __shared__ float  b1s[32];

    int tid = threadIdx.x;
    int blockPos = blockIdx.x * POS;
    int b   = blockPos >> 12;
    int t0b = blockPos & 4095;
    int p0b = t0b*2 - 1;
    int xstart = 2*p0b - 1;

    if (tid < 128) w1s[tid] = w1[tid];
    if (tid < 32)  b1s[tid] = b1[tid];
    for (int i = tid; i < 262; i += 256) {
        int xi = xstart + i;
        xs[i] = (xi >= 0 && xi < 16384) ? x[b*16384 + xi] : 0.f;
    }
    __syncthreads();

    for (int i = tid; i < PB*C4; i += 256) {
        int pl = i >> 3, c4 = i & 7;
        int pos = p0b + pl;
        float4 v = make_float4(0.f, 0.f, 0.f, 0.f);
        if (pos >= 0 && pos < 8192) {
            float r[4];
            #pragma unroll
            for (int ch = 0; ch < 4; ch++) {
                int co = c4*4 + ch;
                float acc = b1s[co];
                #pragma unroll
                for (int j = 0; j < 4; j++) acc += w1s[co*4 + j] * xs[2*pl + j];
                r[ch] = fmaxf(acc, 0.f);
            }
            v = make_float4(r[0], r[1], r[2], r[3]);
        }
        is[i] = v;
    }
    __syncthreads();

    int ty = tid % TY, tx = tid / TY, tloc = tx * TT;
    const float4* wt4 = reinterpret_cast<const float4*>(wt2);

    float4 acc[TT];
    #pragma unroll
    for (int t = 0; t < TT; t++) acc[t] = make_float4(0.f, 0.f, 0.f, 0.f);

    for (int c4 = 0; c4 < C4; c4++) {
        float4 iv[SPAN];
        #pragma unroll
        for (int s = 0; s < SPAN; s++) iv[s] = is[(tloc*S + s)*C4 + c4];
        #pragma unroll
        for (int j = 0; j < K; j++) {
            float4 w0 = __ldg(&wt4[(j*32 + c4*4 + 0)*CO4 + ty]);
            float4 w1v = __ldg(&wt4[(j*32 + c4*4 + 1)*CO4 + ty]);
            float4 w2 = __ldg(&wt4[(j*32 + c4*4 + 2)*CO4 + ty]);
            float4 w3 = __ldg(&wt4[(j*32 + c4*4 + 3)*CO4 + ty]);
            #pragma unroll
            for (int t = 0; t < TT; t++) {
                float4 xv = iv[t*S + j];
                acc[t].x += w0.x*xv.x + w1v.x*xv.y + w2.x*xv.z + w3.x*xv.w;
                acc[t].y += w0.y*xv.x + w1v.y*xv.y + w2.y*xv.z + w3.y*xv.w;
                acc[t].z += w0.z*xv.x + w1v.z*xv.y + w2.z*xv.z + w3.z*xv.w;
                acc[t].w += w0.w*xv.x + w1v.w*xv.y + w2.w*xv.z + w3.w*xv.w;
            }
        }
    }

    float4 bv = reinterpret_cast<const float4*>(b2)[ty];
    float4* out4 = reinterpret_cast<float4*>(out);
    #pragma unroll
    for (int t = 0; t < TT; t++) {
        float4 v;
        v.x = fmaxf(acc[t].x + bv.x, 0.f); v.y = fmaxf(acc[t].y + bv.y, 0.f);
        v.z = fmaxf(acc[t].z + bv.z, 0.f); v.w = fmaxf(acc[t].w + bv.w, 0.f);
        out4[(b*4096 + t0b + tloc + t)*CO4 + ty] = v;
    }
}

// ---------------- VQ: exact scalar scan, 8-code ILP (R14 passing version, verbatim) ----------------
__global__ __launch_bounds__(256) void vq2_kernel(const float* __restrict__ z,
                                                  const float* __restrict__ emb,
                                                  float* __restrict__ out,
                                                  int* __restrict__ fidx,
                                                  float* __restrict__ partial,
                                                  int* __restrict__ counts)
{
    __shared__ float4 es[2048];     // 128 codes x 16 float4 = 32KB
    __shared__ float  ek2s[128];
    __shared__ float  red[256];

    int tid = threadIdx.x;
    int row = blockIdx.x * 256 + tid;
    const float4* z4 = reinterpret_cast<const float4*>(z);
    const float4* e4 = reinterpret_cast<const float4*>(emb);

    float4 zv[16];
    #pragma unroll
    for (int dv = 0; dv < 16; dv++) zv[dv] = __ldg(&z4[row*16 + dv]);

    float x2 = 0.f;
    #pragma unroll
    for (int dv = 0; dv < 16; dv++) {
        float4 v = zv[dv];
        x2 += v.x*v.x + v.y*v.y + v.z*v.z + v.w*v.w;
    }

    float best = 3.4e38f;
    int bidx = 0;
    for (int ch = 0; ch < 4; ch++) {
        for (int i = tid; i < 2048; i += 256) es[i] = e4[ch*2048 + i];
        __syncthreads();
        if (tid < 128) {
            float s = 0.f;
            #pragma unroll
            for (int dv = 0; dv < 16; dv++) {
                float4 v = es[tid*16 + dv];
                s += v.x*v.x + v.y*v.y + v.z*v.z + v.w*v.w;
            }
            ek2s[tid] = s;
        }
        __syncthreads();
        for (int c = 0; c < 128; c += 8) {
            float a0 = 0.f, a1 = 0.f, a2 = 0.f, a3 = 0.f;
            float a4 = 0.f, a5 = 0.f, a6 = 0.f, a7 = 0.f;
            #pragma unroll
            for (int dv = 0; dv < 16; dv++) {
                float4 zd = zv[dv];
                float4 e0 = es[(c+0)*16 + dv];
                float4 e1 = es[(c+1)*16 + dv];
                float4 e2 = es[(c+2)*16 + dv];
                float4 e3 = es[(c+3)*16 + dv];
                a0 += e0.x*zd.x + e0.y*zd.y + e0.z*zd.z + e0.w*zd.w;
                a1 += e1.x*zd.x + e1.y*zd.y + e1.z*zd.z + e1.w*zd.w;
                a2 += e2.x*zd.x + e2.y*zd.y + e2.z*zd.z + e2.w*zd.w;
                a3 += e3.x*zd.x + e3.y*zd.y + e3.z*zd.z + e3.w*zd.w;
                float4 e4v = es[(c+4)*16 + dv];
                float4 e5 = es[(c+5)*16 + dv];
                float4 e6 = es[(c+6)*16 + dv];
                float4 e7 = es[(c+7)*16 + dv];
                a4 += e4v.x*zd.x + e4v.y*zd.y + e4v.z*zd.z + e4v.w*zd.w;
                a5 += e5.x*zd.x + e5.y*zd.y + e5.z*zd.z + e5.w*zd.w;
                a6 += e6.x*zd.x + e6.y*zd.y + e6.z*zd.z + e6.w*zd.w;
                a7 += e7.x*zd.x + e7.y*zd.y + e7.z*zd.z + e7.w*zd.w;
            }
            float d0 = (x2 + ek2s[c+0]) - 2.f*a0;
            float d1 = (x2 + ek2s[c+1]) - 2.f*a1;
            float d2 = (x2 + ek2s[c+2]) - 2.f*a2;
            float d3 = (x2 + ek2s[c+3]) - 2.f*a3;
            float d4 = (x2 + ek2s[c+4]) - 2.f*a4;
            float d5 = (x2 + ek2s[c+5]) - 2.f*a5;
            float d6 = (x2 + ek2s[c+6]) - 2.f*a6;
            float d7 = (x2 + ek2s[c+7]) - 2.f*a7;
            int code = ch*128 + c;
            if (d0 < best) { best = d0; bidx = code;     }
            if (d1 < best) { best = d1; bidx = code + 1; }
            if (d2 < best) { best = d2; bidx = code + 2; }
            if (d3 < best) { best = d3; bidx = code + 3; }
            if (d4 < best) { best = d4; bidx = code + 4; }
            if (d5 < best) { best = d5; bidx = code + 5; }
            if (d6 < best) { best = d6; bidx = code + 6; }
            if (d7 < best) { best = d7; bidx = code + 7; }
        }
        __syncthreads();
    }

    out[IDX_OFF + row] = (float)bidx;
    fidx[row] = bidx;
    atomicAdd(&counts[bidx], 1);

    float ls = 0.f;
    #pragma unroll
    for (int dv = 0; dv < 16; dv++) {
        float4 ev = __ldg(&e4[bidx*16 + dv]);
        float4 q = zv[dv];
        float dx = ev.x - q.x, dy = ev.y - q.y, dz = ev.z - q.z, dw = ev.w - q.w;
        ls += dx*dx + dy*dy + dz*dz + dw*dw;
    }
    red[tid] = ls;
    __syncthreads();
    for (int s = 128; s > 0; s >>= 1) {
        if (tid < s) red[tid] += red[tid + s];
        __syncthreads();
    }
    if (tid == 0) partial[blockIdx.x] = red[0];
}

// ---------------- finalize: loss + perplexity ----------------
__global__ void finalize_kernel(const float* __restrict__ partial, const int* __restrict__ counts,
                                float* __restrict__ out)
{
    __shared__ double red[512];
    int tid = threadIdx.x;
    double s = 0.0;
    for (int i = tid; i < 512; i += 512) s += (double)partial[i];
    red[tid] = s;
    __syncthreads();
    for (int st = 256; st > 0; st >>= 1) {
        if (tid < st) red[tid] += red[tid + st];
        __syncthreads();
    }
    if (tid == 0) out[0] = (float)(1.25 * red[0] / 8388608.0);
    __syncthreads();
    double p = (double)counts[tid] / 131072.0;
    double t = p * log(p + 1e-10);
    red[tid] = t;
    __syncthreads();
    for (int st = 256; st > 0; st >>= 1) {
        if (tid < st) red[tid] += red[tid + st];
        __syncthreads();
    }
    if (tid == 0) out[PERP_OFF] = (float)exp(-red[0]);
}

// ---------------- fused dcv3 (G-gather, fidx staged in smem) + dec4 ----------------
__global__ __launch_bounds__(256) void dcv34_kernel(const int* __restrict__ fidx,
                                                    const float* __restrict__ G,
                                                    const float* __restrict__ wt,
                                                    const float* __restrict__ bias,
                                                    const float* __restrict__ wt4d,
                                                    const float* __restrict__ b4d,
                                                    float* __restrict__ out)
{
    constexpr int C4 = 16, CO4 = 16, TY = 16, TT = 4, POS = 64, PB = 67, I4 = PB*C4, SPAN = 6;
    __shared__ float4 is[I4];
    __shared__ float4 res[POS*16];
    __shared__ float4 halo[8];
    __shared__ float4 ws4[32];
    __shared__ int    fs[72];          // fidx for positions p0b-1 .. p0b+67

    int tid = threadIdx.x;
    int blockPos = blockIdx.x * POS;
    int t0b = blockPos & 4095;
    int bbase = blockPos - t0b;
    int b = bbase >> 12;
    int p0b = t0b - 2;
    const float4* G4 = reinterpret_cast<const float4*>(G);

    if (tid < 32) ws4[tid] = reinterpret_cast<const float4*>(wt4d)[tid];
    if (tid < 69) {
        int p = p0b - 1 + tid;
        fs[tid] = (p >= 0 && p < 4096) ? fidx[bbase + p] : 0;
    }
    __syncthreads();

    for (int i = tid; i < I4; i += 256) {
        int pl = i >> 4, c4 = i & 15;
        int p = p0b + pl;
        float4 v = make_float4(0.f, 0.f, 0.f, 0.f);
        if (p >= 0 && p < 4096) {
            int cc = fs[pl + 1];
            v = __ldg(&G4[(512 + cc)*16 + c4]);
            if (p > 0) {
                int cm = fs[pl];
                float4 g = __ldg(&G4[cm*16 + c4]);
                v.x += g.x; v.y += g.y; v.z += g.z; v.w += g.w;
            }
            if (p < 4095) {
                int cp = fs[pl + 2];
                float4 g = __ldg(&G4[(1024 + cp)*16 + c4]);
                v.x += g.x; v.y += g.y; v.z += g.z; v.w += g.w;
            }
            v.x = fmaxf(v.x, 0.f); v.y = fmaxf(v.y, 0.f);
            v.z = fmaxf(v.z, 0.f); v.w = fmaxf(v.w, 0.f);
        }
        is[i] = v;
    }
    __syncthreads();

    int ty = tid % TY, tx = tid / TY, tloc = tx * TT;
    const float4* wt4 = reinterpret_cast<const float4*>(wt);

    if (tid < 8 && t0b > 0) {
        int q = tid + 8;
        ull h01 = 0ull, h23 = 0ull;
        for (int c4 = 0; c4 < C4; c4++) {
            #pragma unroll
            for (int j = 0; j < 3; j++) {
                float4 xv = is[j*C4 + c4];
                float4 w0 = __ldg(&wt4[(j*64 + c4*4 + 0)*CO4 + q]);
                float4 w1 = __ldg(&wt4[(j*64 + c4*4 + 1)*CO4 + q]);
                float4 w2 = __ldg(&wt4[(j*64 + c4*4 + 2)*CO4 + q]);
                float4 w3 = __ldg(&wt4[(j*64 + c4*4 + 3)*CO4 + q]);
                ulonglong2 p0 = *reinterpret_cast<ulonglong2*>(&w0);
                ulonglong2 p1 = *reinterpret_cast<ulonglong2*>(&w1);
                ulonglong2 p2 = *reinterpret_cast<ulonglong2*>(&w2);
                ulonglong2 p3 = *reinterpret_cast<ulonglong2*>(&w3);
                ull d;
                d = pk2(xv.x); FMA2(h01, p0.x, d, h01); FMA2(h23, p0.y, d, h23);
                d = pk2(xv.y); FMA2(h01, p1.x, d, h01); FMA2(h23, p1.y, d, h23);
                d = pk2(xv.z); FMA2(h01, p2.x, d, h01); FMA2(h23, p2.y, d, h23);
                d = pk2(xv.w); FMA2(h01, p3.x, d, h01); FMA2(h23, p3.y, d, h23);
            }
        }
        float4 bv = reinterpret_cast<const float4*>(bias)[q];
        float x0, x1, x2, x3;
        unpk2(h01, x0, x1);
        unpk2(h23, x2, x3);
        float4 v;
        v.x = fmaxf(x0 + bv.x, 0.f); v.y = fmaxf(x1 + bv.y, 0.f);
        v.z = fmaxf(x2 + bv.z, 0.f); v.w = fmaxf(x3 + bv.w, 0.f);
        halo[tid] = v;
    }

    {
        ull a01[TT], a23[TT];
        #pragma unroll
        for (int t = 0; t < TT; t++) { a01[t] = 0ull; a23[t] = 0ull; }

        for (int c4 = 0; c4 < C4; c4++) {
            float4 iv[SPAN];
            #pragma unroll
            for (int s = 0; s < SPAN; s++) iv[s] = is[(tloc + 1 + s)*C4 + c4];
            #pragma unroll
            for (int j = 0; j < 3; j++) {
                float4 w0 = __ldg(&wt4[(j*64 + c4*4 + 0)*CO4 + ty]);
                float4 w1 = __ldg(&wt4[(j*64 + c4*4 + 1)*CO4 + ty]);
                float4 w2 = __ldg(&wt4[(j*64 + c4*4 + 2)*CO4 + ty]);
                float4 w3 = __ldg(&wt4[(j*64 + c4*4 + 3)*CO4 + ty]);
                ulonglong2 p0 = *reinterpret_cast<ulonglong2*>(&w0);
                ulonglong2 p1 = *reinterpret_cast<ulonglong2*>(&w1);
                ulonglong2 p2 = *reinterpret_cast<ulonglong2*>(&w2);
                ulonglong2 p3 = *reinterpret_cast<ulonglong2*>(&w3);
                #pragma unroll
                for (int t = 0; t < TT; t++) {
                    float4 xv = iv[t + j];
                    ull d;
                    d = pk2(xv.x); FMA2(a01[t], p0.x, d, a01[t]); FMA2(a23[t], p0.y, d, a23[t]);
                    d = pk2(xv.y); FMA2(a01[t], p1.x, d, a01[t]); FMA2(a23[t], p1.y, d, a23[t]);
                    d = pk2(xv.z); FMA2(a01[t], p2.x, d, a01[t]); FMA2(a23[t], p2.y, d, a23[t]);
                    d = pk2(xv.w); FMA2(a01[t], p3.x, d, a01[t]); FMA2(a23[t], p3.y, d, a23[t]);
                }
            }
        }

        float4 bv = reinterpret_cast<const float4*>(bias)[ty];
        #pragma unroll
        for (int t = 0; t < TT; t++) {
            float x0, x1, x2, x3;
            unpk2(a01[t], x0, x1);
            unpk2(a23[t], x2, x3);
            float4 v;
            v.x = fmaxf(x0 + bv.x, 0.f); v.y = fmaxf(x1 + bv.y, 0.f);
            v.z = fmaxf(x2 + bv.z, 0.f); v.w = fmaxf(x3 + bv.w, 0.f);
            res[(tloc + t)*16 + ty] = v;
        }
    }
    __syncthreads();

    float b4 = b4d[0];
    int D0 = 2*t0b;
    int l = 4*t0b - 1 + tid;
    if (l >= 0 && l <= 16384) {
        float acc = 0.f;
        int j0 = (l + 1) & 1;
        #pragma unroll
        for (int jj = 0; jj < 2; jj++) {
            int j = j0 + 2*jj;
            int num = l + 1 - j;
            if (num >= 0) {
                int t = num >> 1;
                if (t < 8192) {
                    int dt = t - D0;
                    const float4* src = (dt < 0) ? halo
                                                 : &res[(dt >> 1)*16 + (dt & 1)*8];
                    #pragma unroll
                    for (int c4 = 0; c4 < 8; c4++) {
                        float4 wv = ws4[j*8 + c4];
                        float4 xv = src[c4];
                        acc += wv.x*xv.x + wv.y*xv.y + wv.z*xv.z + wv.w*xv.w;
                    }
                }
            }
        }
        out[1 + b*16385 + l] = acc + b4;
    }
    if (t0b == 4032 && tid < 2) {
        int l2 = 16383 + tid;
        float acc = 0.f;
        int j0 = (l2 + 1) & 1;
        #pragma unroll
        for (int jj = 0; jj < 2; jj++) {
            int j = j0 + 2*jj;
            int num = l2 + 1 - j;
            if (num >= 0) {
                int t = num >> 1;
                if (t < 8192) {
                    int dt = t - D0;
                    const float4* src = &res[(dt >> 1)*16 + (dt & 1)*8];
                    #pragma unroll
                    for (int c4 = 0; c4 < 8; c4++) {
                        float4 wv = ws4[j*8 + c4];
                        float4 xv = src[c4];
                        acc += wv.x*xv.x + wv.y*xv.y + wv.z*xv.z + wv.w*xv.w;
                    }
                }
            }
        }
        out[1 + b*16385 + l2] = acc + b4;
    }
}

// ---------------- launch ----------------
extern "C" void kernel_launch(void* const* d_in, const int* in_sizes, int n_in,
                              void* d_out, int out_size)
{
    const float* x   = (const float*)d_in[0];
    const float* ew1 = (const float*)d_in[1];
    const float* eb1 = (const float*)d_in[2];
    const float* ew2 = (const float*)d_in[3];
    const float* eb2 = (const float*)d_in[4];
    const float* ew3 = (const float*)d_in[5];
    const float* eb3 = (const float*)d_in[6];
    const float* ew4 = (const float*)d_in[7];
    const float* eb4 = (const float*)d_in[8];
    const float* dw1 = (const float*)d_in[9];
    const float* db1 = (const float*)d_in[10];
    const float* dw2 = (const float*)d_in[11];
    const float* db2 = (const float*)d_in[12];
    const float* dw3 = (const float*)d_in[13];
    const float* db3 = (const float*)d_in[14];
    const float* dw4 = (const float*)d_in[15];
    const float* db4 = (const float*)d_in[16];
    const float* emb = (const float*)d_in[17];
    float* out = (float*)d_out;

    float *a2, *a3, *z;
    float *wt2, *wt3, *wt4, *wtd2, *wtd3f, *wtd4, *b3f, *G, *partial;
    int *counts, *fidx;
    cudaGetSymbolAddress((void**)&a2,    g_a2);
    cudaGetSymbolAddress((void**)&a3,    g_a3);
    cudaGetSymbolAddress((void**)&z,     g_z);
    cudaGetSymbolAddress((void**)&wt2,   g_wt2);
    cudaGetSymbolAddress((void**)&wt3,   g_wt3);
    cudaGetSymbolAddress((void**)&wt4,   g_wt4);
    cudaGetSymbolAddress((void**)&wtd2,  g_wtd2);
    cudaGetSymbolAddress((void**)&wtd3f, g_wtd3f);
    cudaGetSymbolAddress((void**)&wtd4,  g_wtd4);
    cudaGetSymbolAddress((void**)&b3f,   g_b3f);
    cudaGetSymbolAddress((void**)&G,     g_G);
    cudaGetSymbolAddress((void**)&partial, g_partial);
    cudaGetSymbolAddress((void**)&counts,  g_counts);
    cudaGetSymbolAddress((void**)&fidx,    g_fidx);

    auto enc4 = convSs<128, 64, 1, 1, 0, false, 8, 2>;
    cudaFuncSetAttribute(enc4, cudaFuncAttributeMaxDynamicSharedMemorySize, 128*32*16);

    // prep (R14 structure: coalesced wtd2 relayout, then G build reading it)
    transform_kernel<<<96, 256>>>(ew2, ew3, ew4, dw2, dw3, db3, dw4,
                                  wt2, wt3, wt4, wtd2, wtd3f, b3f, wtd4, counts);
    build_EG_kernel<<<512, 192>>>(emb, dw1, db1, wtd2, db2, G);

    // encoder — scalar fp32 (index-determining path; per-output chains identical to R8)
    enc12_kernel<<<2048, 256>>>(x, ew1, eb1, wt2, eb2, a2);
    convSs<64, 128, 3, 1, 1, true, 4, 4><<<4096, 256, 34*16*16>>>(a2, wt3, eb3, a3, 4096, 4096);
    enc4<<<1024, 256, 128*32*16>>>(a3, wt4, eb4, z, 4096, 4096);

    // vq — exact scalar scan, 8-code ILP (compiled association = ground truth)
    vq2_kernel<<<512, 256>>>(z, emb, out, fidx, partial, counts);
    finalize_kernel<<<1, 512>>>(partial, counts, out);

    // decoder — fused G-gather conv + dec4, writes recon directly
    dcv34_kernel<<<2048, 256>>>(fidx, G, wtd3f, b3f, wtd4, db4, out);
}